// round 1
// baseline (speedup 1.0000x reference)
#include <cuda_runtime.h>
#include <math_constants.h>
#include <stdint.h>

#define C_CLASSES 1000
#define NB 15
#define NSEG (C_CLASSES * NB)

// Scratch accumulators (no cudaMalloc allowed). Re-zeroed every launch so the
// kernel is graph-replay deterministic.
__device__ float g_colsum[C_CLASSES];   // per-class sum of probs (all bins)
__device__ float g_cnthi[NSEG];         // counts for bins >= 1 (bin0 implicit)
__device__ float g_confhi[NSEG];        // conf sums for bins >= 1
__device__ float g_acc[NSEG];           // label-match counts, all bins

__global__ void ece_zero_kernel() {
    int i = blockIdx.x * blockDim.x + threadIdx.x;
    if (i < C_CLASSES) g_colsum[i] = 0.0f;
    if (i < NSEG) {
        g_cnthi[i]  = 0.0f;
        g_confhi[i] = 0.0f;
        g_acc[i]    = 0.0f;
    }
}

__device__ __forceinline__ void rare_bin(float p, int c) {
    float t = p * (float)NB;
    if (t > 1.0f) {               // bin >= 1 : rare path
        int b = (int)ceilf(t) - 1;
        if (b > NB - 1) b = NB - 1;
        atomicAdd(&g_cnthi[c * NB + b], 1.0f);
        atomicAdd(&g_confhi[c * NB + b], p);
    }
}

__device__ __forceinline__ void acc_add(int label, float p) {
    float t = p * (float)NB;
    int b = (int)ceilf(t) - 1;
    if (b < 0) b = 0;
    if (b > NB - 1) b = NB - 1;
    atomicAdd(&g_acc[label * NB + b], 1.0f);
}

__global__ __launch_bounds__(512)
void ece_main_kernel(const float* __restrict__ logits,
                     const int*   __restrict__ labels,
                     int n) {
    const int t    = threadIdx.x;
    const int lane = t & 31;
    const int warp = t >> 5;
    const int c0   = 2 * t;                 // this thread owns classes c0, c0+1
    const bool valid = (c0 < C_CLASSES);

    __shared__ float sh[34];                // [0..15] row0 partials, [16..31] row1, [32..33] broadcast

    float a0 = 0.0f, a1 = 0.0f;             // register column-sum accumulators

    const int64_t stride = (int64_t)gridDim.x * 2;
    int64_t r = (int64_t)blockIdx.x * 2;

    const float NEG_INF = -CUDART_INF_F;
    float2 x0 = make_float2(NEG_INF, NEG_INF);
    float2 x1 = x0;
    if (valid) {
        if (r < n)     x0 = *(const float2*)(logits + r * C_CLASSES + c0);
        if (r + 1 < n) x1 = *(const float2*)(logits + (r + 1) * C_CLASSES + c0);
    }

    while (r < n) {
        // ---- prefetch next row pair (overlaps with the reductions below) ----
        const int64_t rn = r + stride;
        float2 nx0 = make_float2(NEG_INF, NEG_INF);
        float2 nx1 = nx0;
        if (valid) {
            if (rn < n)     nx0 = *(const float2*)(logits + rn * C_CLASSES + c0);
            if (rn + 1 < n) nx1 = *(const float2*)(logits + (rn + 1) * C_CLASSES + c0);
        }

        const bool has1 = (r + 1 < n);
        const int  l0 = labels[r];
        const int  l1 = has1 ? labels[r + 1] : -1;

        // ---- block-reduce max for both rows ----
        float m0 = fmaxf(x0.x, x0.y);
        float m1 = fmaxf(x1.x, x1.y);
        #pragma unroll
        for (int o = 16; o; o >>= 1) {
            m0 = fmaxf(m0, __shfl_xor_sync(0xFFFFFFFFu, m0, o));
            m1 = fmaxf(m1, __shfl_xor_sync(0xFFFFFFFFu, m1, o));
        }
        if (lane == 0) { sh[warp] = m0; sh[16 + warp] = m1; }
        __syncthreads();
        if (warp == 0) {
            float v0 = (lane < 16) ? sh[lane]      : NEG_INF;
            float v1 = (lane < 16) ? sh[16 + lane] : NEG_INF;
            #pragma unroll
            for (int o = 8; o; o >>= 1) {
                v0 = fmaxf(v0, __shfl_xor_sync(0xFFFFFFFFu, v0, o));
                v1 = fmaxf(v1, __shfl_xor_sync(0xFFFFFFFFu, v1, o));
            }
            if (lane == 0) { sh[32] = v0; sh[33] = v1; }
        }
        __syncthreads();
        m0 = sh[32];
        m1 = sh[33];

        // ---- exp (invalid lanes have x = -inf -> e = 0) ----
        float e00 = __expf(x0.x - m0);
        float e01 = __expf(x0.y - m0);
        float e10 = has1 ? __expf(x1.x - m1) : 0.0f;
        float e11 = has1 ? __expf(x1.y - m1) : 0.0f;

        // ---- block-reduce sum for both rows, broadcast reciprocals ----
        float s0 = e00 + e01;
        float s1 = e10 + e11;
        #pragma unroll
        for (int o = 16; o; o >>= 1) {
            s0 += __shfl_xor_sync(0xFFFFFFFFu, s0, o);
            s1 += __shfl_xor_sync(0xFFFFFFFFu, s1, o);
        }
        if (lane == 0) { sh[warp] = s0; sh[16 + warp] = s1; }
        __syncthreads();
        if (warp == 0) {
            float v0 = (lane < 16) ? sh[lane]      : 0.0f;
            float v1 = (lane < 16) ? sh[16 + lane] : 0.0f;
            #pragma unroll
            for (int o = 8; o; o >>= 1) {
                v0 += __shfl_xor_sync(0xFFFFFFFFu, v0, o);
                v1 += __shfl_xor_sync(0xFFFFFFFFu, v1, o);
            }
            if (lane == 0) {
                sh[32] = 1.0f / v0;
                sh[33] = (v1 > 0.0f) ? (1.0f / v1) : 0.0f;
            }
        }
        __syncthreads();
        const float inv0 = sh[32];
        const float inv1 = sh[33];

        // ---- probs, register accumulation, rare bins, label bin ----
        float p00 = e00 * inv0, p01 = e01 * inv0;
        float p10 = e10 * inv1, p11 = e11 * inv1;
        a0 += p00 + p10;
        a1 += p01 + p11;

        if (valid) {
            rare_bin(p00, c0);
            rare_bin(p01, c0 + 1);
            if (has1) {
                rare_bin(p10, c0);
                rare_bin(p11, c0 + 1);
            }
            if (l0 == c0)     acc_add(l0, p00);
            if (l0 == c0 + 1) acc_add(l0, p01);
            if (l1 == c0)     acc_add(l1, p10);
            if (l1 == c0 + 1) acc_add(l1, p11);
        }

        x0 = nx0; x1 = nx1; r = rn;
    }

    if (valid) {
        atomicAdd(&g_colsum[c0],     a0);
        atomicAdd(&g_colsum[c0 + 1], a1);
    }
}

__global__ __launch_bounds__(1024)
void ece_final_kernel(float* __restrict__ out, int n) {
    const int c    = threadIdx.x;
    const int lane = c & 31;
    const int warp = c >> 5;

    float sce = 0.0f;
    if (c < C_CLASSES) {
        const float invn = 1.0f / (float)n;
        float hiCnt = 0.0f, hiConf = 0.0f;
        #pragma unroll
        for (int b = 1; b < NB; b++) {
            hiCnt  += g_cnthi[c * NB + b];
            hiConf += g_confhi[c * NB + b];
        }
        // bin 0 (implicit)
        {
            float cnt0  = (float)n - hiCnt;
            float conf0 = g_colsum[c] - hiConf;
            float acc0  = g_acc[c * NB + 0];
            if (cnt0 > 0.0f)
                sce += fabsf(conf0 - acc0) / cnt0 * (cnt0 * invn);
        }
        #pragma unroll
        for (int b = 1; b < NB; b++) {
            float cb = g_cnthi[c * NB + b];
            if (cb > 0.0f) {
                float confb = g_confhi[c * NB + b];
                float accb  = g_acc[c * NB + b];
                sce += fabsf(confb - accb) / cb * (cb * invn);
            }
        }
    }

    __shared__ float sh[32];
    #pragma unroll
    for (int o = 16; o; o >>= 1) sce += __shfl_xor_sync(0xFFFFFFFFu, sce, o);
    if (lane == 0) sh[warp] = sce;
    __syncthreads();
    if (warp == 0) {
        float v = sh[lane];
        #pragma unroll
        for (int o = 16; o; o >>= 1) v += __shfl_xor_sync(0xFFFFFFFFu, v, o);
        if (lane == 0) out[0] = v / (float)C_CLASSES;
    }
}

extern "C" void kernel_launch(void* const* d_in, const int* in_sizes, int n_in,
                              void* d_out, int out_size) {
    const float* logits = (const float*)d_in[0];
    const int*   labels = (const int*)d_in[1];
    const int n = in_sizes[1];              // number of rows = label count

    ece_zero_kernel<<<(NSEG + 255) / 256, 256>>>();
    ece_main_kernel<<<512, 512>>>(logits, labels, n);
    ece_final_kernel<<<1, 1024>>>((float*)d_out, n);
}

// round 2
// speedup vs baseline: 3.3140x; 3.3140x over previous
#include <cuda_runtime.h>
#include <math_constants.h>
#include <stdint.h>

#define C_CLASSES 1000
#define NB 15
#define NSEG (C_CLASSES * NB)
#define NF4 250            // float4 chunks per row
#define JMAX 8             // ceil(NF4/32)

// Scratch accumulators (no cudaMalloc allowed). Re-zeroed every launch so the
// kernel is graph-replay deterministic.
__device__ float g_colsum[C_CLASSES];   // per-class sum of probs (all bins)
__device__ float g_cnthi[NSEG];         // counts for bins >= 1 (bin0 implicit)
__device__ float g_confhi[NSEG];        // conf sums for bins >= 1
__device__ float g_acc[NSEG];           // label-match counts, all bins

__global__ void ece_zero_kernel() {
    int i = blockIdx.x * blockDim.x + threadIdx.x;
    if (i < C_CLASSES) g_colsum[i] = 0.0f;
    if (i < NSEG) {
        g_cnthi[i]  = 0.0f;
        g_confhi[i] = 0.0f;
        g_acc[i]    = 0.0f;
    }
}

__device__ __forceinline__ float ex2(float x) {
    float y;
    asm("ex2.approx.ftz.f32 %0, %1;" : "=f"(y) : "f"(x));
    return y;
}

__global__ __launch_bounds__(256, 2)
void ece_main_kernel(const float* __restrict__ logits,
                     const int*   __restrict__ labels,
                     int n) {
    const int lane = threadIdx.x & 31;
    const int wIn  = threadIdx.x >> 5;
    const int gw   = blockIdx.x * (blockDim.x >> 5) + wIn;   // global warp id
    const int W    = gridDim.x * (blockDim.x >> 5);          // total warps

    __shared__ float shc[C_CLASSES];
    for (int i = threadIdx.x; i < C_CLASSES; i += blockDim.x) shc[i] = 0.0f;
    __syncthreads();

    // Per-thread column-sum accumulators: class 4*(j*32+lane)+k -> acc[j*4+k]
    float acc[32];
    #pragma unroll
    for (int i = 0; i < 32; i++) acc[i] = 0.0f;

    const float L2E = 1.4426950408889634f;
    const float NEG = -CUDART_INF_F;

    for (int r = gw; r < n; r += W) {
        const float* row = logits + (size_t)r * C_CLASSES;

        // ---- load: lane holds float4 at indices j*32+lane ----
        float4 v[JMAX];
        #pragma unroll
        for (int j = 0; j < JMAX; j++) {
            int idx = j * 32 + lane;
            if (idx < NF4) v[j] = *(const float4*)(row + idx * 4);
            else           v[j] = make_float4(NEG, NEG, NEG, NEG);
        }

        // ---- row max: local tree + warp butterfly (no smem, no bar.sync) ----
        float m = NEG;
        #pragma unroll
        for (int j = 0; j < JMAX; j++) {
            float a = fmaxf(v[j].x, v[j].y);
            float b = fmaxf(v[j].z, v[j].w);
            m = fmaxf(m, fmaxf(a, b));
        }
        #pragma unroll
        for (int o = 16; o; o >>= 1)
            m = fmaxf(m, __shfl_xor_sync(0xFFFFFFFFu, m, o));

        // ---- exp via single MUFU per element: e = 2^(x*L2E - m*L2E) ----
        const float m2 = m * L2E;
        float e[32];
        #pragma unroll
        for (int j = 0; j < JMAX; j++) {
            e[j * 4 + 0] = ex2(fmaf(v[j].x, L2E, -m2));
            e[j * 4 + 1] = ex2(fmaf(v[j].y, L2E, -m2));
            e[j * 4 + 2] = ex2(fmaf(v[j].z, L2E, -m2));
            e[j * 4 + 3] = ex2(fmaf(v[j].w, L2E, -m2));
        }

        // ---- row sum: local tree + warp butterfly ----
        float s = 0.0f;
        #pragma unroll
        for (int j = 0; j < JMAX; j++)
            s += (e[j * 4 + 0] + e[j * 4 + 1]) + (e[j * 4 + 2] + e[j * 4 + 3]);
        #pragma unroll
        for (int o = 16; o; o >>= 1)
            s += __shfl_xor_sync(0xFFFFFFFFu, s, o);

        const float inv = __fdividef(1.0f, s);

        // ---- accumulate per-class prob sums in registers (32 FFMA) ----
        #pragma unroll
        for (int i = 0; i < 32; i++)
            acc[i] = fmaf(e[i], inv, acc[i]);

        // ---- label bin: one atomic per row, handled by the owning lane ----
        const int lab = __ldg(labels + r);
        if (((lab >> 2) & 31) == lane) {
            float xl = __ldg(row + lab);               // L1 hit (row just read)
            float p  = ex2(fmaf(xl, L2E, -m2)) * inv;
            int   b  = __float2int_ru(p * (float)NB) - 1;
            b = max(0, min(NB - 1, b));
            atomicAdd(&g_acc[lab * NB + b], 1.0f);
        }

        // ---- rare path: any p > 1/NB possible iff s < NB (max e == 1) ----
        if (s < (float)NB) {
            #pragma unroll
            for (int j = 0; j < JMAX; j++) {
                int idx = j * 32 + lane;
                if (idx < NF4) {
                    #pragma unroll
                    for (int k = 0; k < 4; k++) {
                        float p = e[j * 4 + k] * inv;
                        float t = p * (float)NB;
                        if (t > 1.0f) {
                            int b = __float2int_ru(t) - 1;
                            if (b > NB - 1) b = NB - 1;
                            int c = (idx * 4 + k);
                            atomicAdd(&g_cnthi[c * NB + b], 1.0f);
                            atomicAdd(&g_confhi[c * NB + b], p);
                        }
                    }
                }
            }
        }
    }

    // ---- flush register accumulators: smem reduce, then 1000 REDG per block ----
    #pragma unroll
    for (int j = 0; j < JMAX; j++) {
        int idx = j * 32 + lane;
        if (idx < NF4) {
            #pragma unroll
            for (int k = 0; k < 4; k++)
                atomicAdd(&shc[idx * 4 + k], acc[j * 4 + k]);
        }
    }
    __syncthreads();
    for (int i = threadIdx.x; i < C_CLASSES; i += blockDim.x)
        atomicAdd(&g_colsum[i], shc[i]);
}

__global__ __launch_bounds__(1024)
void ece_final_kernel(float* __restrict__ out, int n) {
    const int c    = threadIdx.x;
    const int lane = c & 31;
    const int warp = c >> 5;

    float sce = 0.0f;
    if (c < C_CLASSES) {
        const float invn = 1.0f / (float)n;
        float hiCnt = 0.0f, hiConf = 0.0f;
        #pragma unroll
        for (int b = 1; b < NB; b++) {
            hiCnt  += g_cnthi[c * NB + b];
            hiConf += g_confhi[c * NB + b];
        }
        // bin 0 (implicit: totals minus rare bins)
        {
            float cnt0  = (float)n - hiCnt;
            float conf0 = g_colsum[c] - hiConf;
            float acc0  = g_acc[c * NB + 0];
            if (cnt0 > 0.0f)
                sce += fabsf(conf0 - acc0) / cnt0 * (cnt0 * invn);
        }
        #pragma unroll
        for (int b = 1; b < NB; b++) {
            float cb = g_cnthi[c * NB + b];
            if (cb > 0.0f) {
                float confb = g_confhi[c * NB + b];
                float accb  = g_acc[c * NB + b];
                sce += fabsf(confb - accb) / cb * (cb * invn);
            }
        }
    }

    __shared__ float sh[32];
    #pragma unroll
    for (int o = 16; o; o >>= 1) sce += __shfl_xor_sync(0xFFFFFFFFu, sce, o);
    if (lane == 0) sh[warp] = sce;
    __syncthreads();
    if (warp == 0) {
        float v = sh[lane];
        #pragma unroll
        for (int o = 16; o; o >>= 1) v += __shfl_xor_sync(0xFFFFFFFFu, v, o);
        if (lane == 0) out[0] = v / (float)C_CLASSES;
    }
}

extern "C" void kernel_launch(void* const* d_in, const int* in_sizes, int n_in,
                              void* d_out, int out_size) {
    const float* logits = (const float*)d_in[0];
    const int*   labels = (const int*)d_in[1];
    const int n = in_sizes[1];              // number of rows = label count

    ece_zero_kernel<<<(NSEG + 255) / 256, 256>>>();
    ece_main_kernel<<<296, 256>>>(logits, labels, n);
    ece_final_kernel<<<1, 1024>>>((float*)d_out, n);
}

// round 3
// speedup vs baseline: 3.8169x; 1.1517x over previous
#include <cuda_runtime.h>
#include <math_constants.h>
#include <stdint.h>

#define C_CLASSES 1000
#define NB 15
#define NSEG (C_CLASSES * NB)
#define NF4 250            // float4 chunks per row
#define JMAX 8             // ceil(NF4/32)

// Scratch accumulators. Zero-initialized at module load; the final kernel
// re-zeros them after consuming, so every kernel_launch call (and every graph
// replay) starts from zeros. No separate zeroing launch needed.
__device__ float g_colsum[C_CLASSES];   // per-class sum of probs (all bins)
__device__ float g_cnthi[NSEG];         // counts for bins >= 1 (bin0 implicit)
__device__ float g_confhi[NSEG];        // conf sums for bins >= 1
__device__ float g_acc[NSEG];           // label-match counts, all bins

__device__ __forceinline__ float ex2(float x) {
    float y;
    asm("ex2.approx.ftz.f32 %0, %1;" : "=f"(y) : "f"(x));
    return y;
}

__global__ __launch_bounds__(256, 2)
void ece_main_kernel(const float* __restrict__ logits,
                     const int*   __restrict__ labels,
                     int n) {
    const int lane = threadIdx.x & 31;
    const int wIn  = threadIdx.x >> 5;
    const int gw   = blockIdx.x * (blockDim.x >> 5) + wIn;   // global warp id
    const int W    = gridDim.x * (blockDim.x >> 5);          // total warps

    __shared__ float shc[C_CLASSES];
    for (int i = threadIdx.x; i < C_CLASSES; i += blockDim.x) shc[i] = 0.0f;
    __syncthreads();

    // Per-thread column-sum accumulators: class 4*(j*32+lane)+k -> acc[j*4+k]
    float acc[32];
    #pragma unroll
    for (int i = 0; i < 32; i++) acc[i] = 0.0f;

    const float L2E = 1.4426950408889634f;
    const float NEG = -CUDART_INF_F;

    int r = gw;

    // ---- prologue: load first row ----
    float4 v[JMAX];
    int lab = 0;
    if (r < n) {
        const float* row = logits + (size_t)r * C_CLASSES;
        #pragma unroll
        for (int j = 0; j < JMAX; j++) {
            int idx = j * 32 + lane;
            v[j] = (idx < NF4) ? *(const float4*)(row + idx * 4)
                               : make_float4(NEG, NEG, NEG, NEG);
        }
        lab = __ldg(labels + r);
    }

    while (r < n) {
        const int rn = r + W;

        // ---- prefetch next row: overlaps this row's entire compute chain ----
        float4 nv[JMAX];
        int nlab = 0;
        if (rn < n) {
            const float* nrow = logits + (size_t)rn * C_CLASSES;
            #pragma unroll
            for (int j = 0; j < JMAX; j++) {
                int idx = j * 32 + lane;
                nv[j] = (idx < NF4) ? *(const float4*)(nrow + idx * 4)
                                    : make_float4(NEG, NEG, NEG, NEG);
            }
            nlab = __ldg(labels + rn);
        }

        // ---- row max: local tree + warp butterfly ----
        float m = NEG;
        #pragma unroll
        for (int j = 0; j < JMAX; j++) {
            float a = fmaxf(v[j].x, v[j].y);
            float b = fmaxf(v[j].z, v[j].w);
            m = fmaxf(m, fmaxf(a, b));
        }
        #pragma unroll
        for (int o = 16; o; o >>= 1)
            m = fmaxf(m, __shfl_xor_sync(0xFFFFFFFFu, m, o));

        // ---- exp via single MUFU per element: e = 2^(x*L2E - m*L2E) ----
        const float m2 = m * L2E;
        float e[32];
        #pragma unroll
        for (int j = 0; j < JMAX; j++) {
            e[j * 4 + 0] = ex2(fmaf(v[j].x, L2E, -m2));
            e[j * 4 + 1] = ex2(fmaf(v[j].y, L2E, -m2));
            e[j * 4 + 2] = ex2(fmaf(v[j].z, L2E, -m2));
            e[j * 4 + 3] = ex2(fmaf(v[j].w, L2E, -m2));
        }

        // ---- row sum: local tree + warp butterfly ----
        float s = 0.0f;
        #pragma unroll
        for (int j = 0; j < JMAX; j++)
            s += (e[j * 4 + 0] + e[j * 4 + 1]) + (e[j * 4 + 2] + e[j * 4 + 3]);
        #pragma unroll
        for (int o = 16; o; o >>= 1)
            s += __shfl_xor_sync(0xFFFFFFFFu, s, o);

        const float inv = __fdividef(1.0f, s);

        // ---- accumulate per-class prob sums in registers (32 FFMA) ----
        #pragma unroll
        for (int i = 0; i < 32; i++)
            acc[i] = fmaf(e[i], inv, acc[i]);

        // ---- label bin: one atomic per row, handled by the owning lane ----
        if (((lab >> 2) & 31) == lane) {
            float xl = __ldg(logits + (size_t)r * C_CLASSES + lab); // L1/L2 hit
            float p  = ex2(fmaf(xl, L2E, -m2)) * inv;
            int   b  = __float2int_ru(p * (float)NB) - 1;
            b = max(0, min(NB - 1, b));
            atomicAdd(&g_acc[lab * NB + b], 1.0f);
        }

        // ---- rare path: any p > 1/NB possible iff s < NB (since max e == 1) ----
        if (s < (float)NB) {
            #pragma unroll
            for (int j = 0; j < JMAX; j++) {
                int idx = j * 32 + lane;
                if (idx < NF4) {
                    #pragma unroll
                    for (int k = 0; k < 4; k++) {
                        float p = e[j * 4 + k] * inv;
                        float t = p * (float)NB;
                        if (t > 1.0f) {
                            int b = __float2int_ru(t) - 1;
                            if (b > NB - 1) b = NB - 1;
                            int c = (idx * 4 + k);
                            atomicAdd(&g_cnthi[c * NB + b], 1.0f);
                            atomicAdd(&g_confhi[c * NB + b], p);
                        }
                    }
                }
            }
        }

        #pragma unroll
        for (int j = 0; j < JMAX; j++) v[j] = nv[j];
        lab = nlab;
        r = rn;
    }

    // ---- flush register accumulators: smem reduce, then 1000 REDG per block ----
    #pragma unroll
    for (int j = 0; j < JMAX; j++) {
        int idx = j * 32 + lane;
        if (idx < NF4) {
            #pragma unroll
            for (int k = 0; k < 4; k++)
                atomicAdd(&shc[idx * 4 + k], acc[j * 4 + k]);
        }
    }
    __syncthreads();
    for (int i = threadIdx.x; i < C_CLASSES; i += blockDim.x)
        atomicAdd(&g_colsum[i], shc[i]);
}

__global__ __launch_bounds__(1024)
void ece_final_kernel(float* __restrict__ out, int n) {
    const int c    = threadIdx.x;
    const int lane = c & 31;
    const int warp = c >> 5;

    float sce = 0.0f;
    if (c < C_CLASSES) {
        const float invn = 1.0f / (float)n;
        float hiCnt = 0.0f, hiConf = 0.0f;
        #pragma unroll
        for (int b = 1; b < NB; b++) {
            hiCnt  += g_cnthi[c * NB + b];
            hiConf += g_confhi[c * NB + b];
        }
        // bin 0 (implicit: totals minus rare bins)
        {
            float cnt0  = (float)n - hiCnt;
            float conf0 = g_colsum[c] - hiConf;
            float acc0  = g_acc[c * NB + 0];
            if (cnt0 > 0.0f)
                sce += fabsf(conf0 - acc0) / cnt0 * (cnt0 * invn);
        }
        #pragma unroll
        for (int b = 1; b < NB; b++) {
            float cb = g_cnthi[c * NB + b];
            if (cb > 0.0f) {
                float confb = g_confhi[c * NB + b];
                float accb  = g_acc[c * NB + b];
                sce += fabsf(confb - accb) / cb * (cb * invn);
            }
        }
    }

    __shared__ float sh[32];
    #pragma unroll
    for (int o = 16; o; o >>= 1) sce += __shfl_xor_sync(0xFFFFFFFFu, sce, o);
    if (lane == 0) sh[warp] = sce;
    __syncthreads();
    if (warp == 0) {
        float v = sh[lane];
        #pragma unroll
        for (int o = 16; o; o >>= 1) v += __shfl_xor_sync(0xFFFFFFFFu, v, o);
        if (lane == 0) out[0] = v / (float)C_CLASSES;
    }

    // ---- restore scratch to zero for the next launch / graph replay ----
    __syncthreads();   // everyone done reading g_* above
    if (c < C_CLASSES) g_colsum[c] = 0.0f;
    for (int i = c; i < NSEG; i += 1024) {
        g_cnthi[i]  = 0.0f;
        g_confhi[i] = 0.0f;
        g_acc[i]    = 0.0f;
    }
}

extern "C" void kernel_launch(void* const* d_in, const int* in_sizes, int n_in,
                              void* d_out, int out_size) {
    const float* logits = (const float*)d_in[0];
    const int*   labels = (const int*)d_in[1];
    const int n = in_sizes[1];              // number of rows = label count

    ece_main_kernel<<<296, 256>>>(logits, labels, n);
    ece_final_kernel<<<1, 1024>>>((float*)d_out, n);
}